// round 2
// baseline (speedup 1.0000x reference)
#include <cuda_runtime.h>
#include <cuda_bf16.h>
#include <math.h>

// Problem constants (fixed by the reference: B=4, H=W=256, C=192, 6 heads, 8x8 windows)
#define BATCH   4
#define HDIM    256
#define WDIM    256
#define CH      192
#define NHEAD   6
#define HEADD   32
#define WS      8
#define NTOK    64            // tokens per window = 8*8
#define NWIN_X  32            // 256/8
#define NWIN_Y  32
#define M_ROWS  (BATCH * HDIM * WDIM)   // 262144
#define QKV_N   (3 * CH)                // 576

// Scratch (allocation-free rule: __device__ globals; allocated at module load,
// outside kernel_launch, which is what the _HX_ENFORCE guards require).
__device__ float g_qkv [(size_t)M_ROWS * QKV_N];   // 604 MB: q|k|v per spatial row
__device__ float g_attn[(size_t)M_ROWS * CH];      // 201 MB: attention out, spatial layout

// ---------------------------------------------------------------------------
// SGEMM with bias: C[M,N] = A[M,K] @ W[N,K]^T + bias[N]
// A row-major (lda=K), W row-major (ldw=K), C row-major (ldc=N).
// BM=128, BN=64, BK=8, 256 threads, 8x4 per-thread micro-tile.
// All calls here satisfy M%128==0, N%64==0, K%8==0.
// ---------------------------------------------------------------------------
__global__ __launch_bounds__(256)
void gemm_bias_kernel(const float* __restrict__ A, const float* __restrict__ W,
                      const float* __restrict__ bias, float* __restrict__ C,
                      int M, int N, int K)
{
    constexpr int BM = 128, BN = 64, BK = 8, TM = 8, TN = 4;
    __shared__ float As[BK][BM];
    __shared__ float Bs[BK][BN];

    const int t  = threadIdx.x;
    const int tx = t & 15;        // 0..15 -> column group (TN=4)
    const int ty = t >> 4;        // 0..15 -> row group (TM=8)

    const int rowBase = blockIdx.y * BM;
    const int colBase = blockIdx.x * BN;

    // A tile load mapping: 128x8 floats = 256 float4
    const int a_row = t >> 1;           // 0..127
    const int a_col = (t & 1) * 4;      // 0 or 4
    // W tile load mapping: 64x8 floats = 128 float4 (threads 0..127)
    const int w_row = (t & 127) >> 1;   // 0..63
    const int w_col = (t & 1) * 4;

    const float* Aptr = A + (size_t)rowBase * K;
    const float* Wptr = W + (size_t)colBase * K;

    float acc[TM][TN];
#pragma unroll
    for (int i = 0; i < TM; i++)
#pragma unroll
        for (int j = 0; j < TN; j++) acc[i][j] = 0.f;

    for (int k0 = 0; k0 < K; k0 += BK) {
        float4 av = *(const float4*)(Aptr + (size_t)a_row * K + k0 + a_col);
        As[a_col + 0][a_row] = av.x;
        As[a_col + 1][a_row] = av.y;
        As[a_col + 2][a_row] = av.z;
        As[a_col + 3][a_row] = av.w;
        if (t < 128) {
            float4 wv = *(const float4*)(Wptr + (size_t)w_row * K + k0 + w_col);
            Bs[w_col + 0][w_row] = wv.x;
            Bs[w_col + 1][w_row] = wv.y;
            Bs[w_col + 2][w_row] = wv.z;
            Bs[w_col + 3][w_row] = wv.w;
        }
        __syncthreads();

#pragma unroll
        for (int kk = 0; kk < BK; kk++) {
            float ra[TM], rb[TN];
            *(float4*)&ra[0] = *(const float4*)&As[kk][ty * TM];
            *(float4*)&ra[4] = *(const float4*)&As[kk][ty * TM + 4];
            *(float4*)&rb[0] = *(const float4*)&Bs[kk][tx * TN];
#pragma unroll
            for (int i = 0; i < TM; i++)
#pragma unroll
                for (int j = 0; j < TN; j++)
                    acc[i][j] = fmaf(ra[i], rb[j], acc[i][j]);
        }
        __syncthreads();
    }

    const float4 bv = *(const float4*)(bias + colBase + tx * TN);
#pragma unroll
    for (int i = 0; i < TM; i++) {
        const size_t r = (size_t)(rowBase + ty * TM + i);
        float4 cv;
        cv.x = acc[i][0] + bv.x;
        cv.y = acc[i][1] + bv.y;
        cv.z = acc[i][2] + bv.z;
        cv.w = acc[i][3] + bv.w;
        *(float4*)(C + r * N + colBase + tx * TN) = cv;
    }
}

// ---------------------------------------------------------------------------
// Window attention. One block per (window, head); 64 threads = 1 per query token.
// Reads q,k,v slices from g_qkv (spatial row layout), writes attention output
// into g_attn in spatial layout (window partition/reverse folded into indexing).
// ---------------------------------------------------------------------------
__global__ __launch_bounds__(64)
void window_attn_kernel(const float* __restrict__ qkv,
                        const float* __restrict__ rpb,   // (225, 6)
                        float* __restrict__ out)
{
    const int win = blockIdx.x;          // 0..4095
    const int h   = blockIdx.y;          // 0..5
    const int b   = win >> 10;           // /1024
    const int wy  = (win >> 5) & 31;
    const int wx  = win & 31;

    const int n   = threadIdx.x;         // query token 0..63
    const int tyn = n >> 3;              // query y within window
    const int txn = n & 7;               // query x within window

    const int y = wy * WS + tyn;
    const int x = wx * WS + txn;
    const size_t row_n = (size_t)b * (HDIM * WDIM) + (size_t)y * WDIM + x;
    const float* qrow = qkv + row_n * QKV_N + h * HEADD;

    __shared__ float ks[NTOK][HEADD];
    __shared__ float vs[NTOK][HEADD];

    // Each thread stages the k and v rows of its own token.
    {
        const float4* kp = (const float4*)(qrow + CH);       // k at offset 192
        const float4* vp = (const float4*)(qrow + 2 * CH);   // v at offset 384
        float4* kd = (float4*)ks[n];
        float4* vd = (float4*)vs[n];
#pragma unroll
        for (int i = 0; i < HEADD / 4; i++) { kd[i] = kp[i]; vd[i] = vp[i]; }
    }

    // q row into registers
    float q[HEADD];
    {
        const float4* qp = (const float4*)qrow;
#pragma unroll
        for (int i = 0; i < HEADD / 4; i++) ((float4*)q)[i] = qp[i];
    }
    __syncthreads();

    const float scale = 0.17677669529663687f;   // 1/sqrt(32)

    float s[NTOK];
#pragma unroll
    for (int m = 0; m < NTOK; m++) {
        float a = 0.f;
        const float4* kp = (const float4*)ks[m];
#pragma unroll
        for (int i = 0; i < HEADD / 4; i++) {
            float4 kv = kp[i];
            a = fmaf(q[i * 4 + 0], kv.x, a);
            a = fmaf(q[i * 4 + 1], kv.y, a);
            a = fmaf(q[i * 4 + 2], kv.z, a);
            a = fmaf(q[i * 4 + 3], kv.w, a);
        }
        const int tym = m >> 3;
        const int txm = m & 7;
        const int idx = (tyn - tym + 7) * 15 + (txn - txm + 7);
        s[m] = fmaf(a, scale, __ldg(rpb + idx * NHEAD + h));
    }

    // softmax over m
    float mx = -1e30f;
#pragma unroll
    for (int m = 0; m < NTOK; m++) mx = fmaxf(mx, s[m]);
    float sum = 0.f;
#pragma unroll
    for (int m = 0; m < NTOK; m++) { s[m] = __expf(s[m] - mx); sum += s[m]; }
    const float inv = 1.0f / sum;

    float o[HEADD];
#pragma unroll
    for (int d = 0; d < HEADD; d++) o[d] = 0.f;
#pragma unroll
    for (int m = 0; m < NTOK; m++) {
        const float p = s[m] * inv;
        const float4* vp = (const float4*)vs[m];
#pragma unroll
        for (int i = 0; i < HEADD / 4; i++) {
            float4 vv = vp[i];
            o[i * 4 + 0] = fmaf(p, vv.x, o[i * 4 + 0]);
            o[i * 4 + 1] = fmaf(p, vv.y, o[i * 4 + 1]);
            o[i * 4 + 2] = fmaf(p, vv.z, o[i * 4 + 2]);
            o[i * 4 + 3] = fmaf(p, vv.w, o[i * 4 + 3]);
        }
    }

    float* orow = out + row_n * CH + h * HEADD;
#pragma unroll
    for (int i = 0; i < HEADD / 4; i++)
        ((float4*)orow)[i] = ((float4*)o)[i];
}

// ---------------------------------------------------------------------------
// launch
// ---------------------------------------------------------------------------
extern "C" void kernel_launch(void* const* d_in, const int* in_sizes, int n_in,
                              void* d_out, int out_size)
{
    const float* x      = (const float*)d_in[0];
    const float* qkv_w  = (const float*)d_in[1];
    const float* qkv_b  = (const float*)d_in[2];
    const float* proj_w = (const float*)d_in[3];
    const float* proj_b = (const float*)d_in[4];
    const float* rpb    = (const float*)d_in[5];
    float* out = (float*)d_out;

    float *qkv_ptr, *attn_ptr;
    cudaGetSymbolAddress((void**)&qkv_ptr,  g_qkv);
    cudaGetSymbolAddress((void**)&attn_ptr, g_attn);

    // 1) QKV projection: (262144 x 192) @ (576 x 192)^T + b -> g_qkv
    gemm_bias_kernel<<<dim3(QKV_N / 64, M_ROWS / 128), 256>>>(
        x, qkv_w, qkv_b, qkv_ptr, M_ROWS, QKV_N, CH);

    // 2) Window attention per (window, head) -> g_attn (spatial layout)
    window_attn_kernel<<<dim3(BATCH * NWIN_Y * NWIN_X, NHEAD), 64>>>(
        qkv_ptr, rpb, attn_ptr);

    // 3) Output projection: (262144 x 192) @ (192 x 192)^T + b -> out
    gemm_bias_kernel<<<dim3(CH / 64, M_ROWS / 128), 256>>>(
        attn_ptr, proj_w, proj_b, out, M_ROWS, CH, CH);
}

// round 3
// speedup vs baseline: 1.2274x; 1.2274x over previous
#include <cuda_runtime.h>
#include <cuda_bf16.h>
#include <math.h>
#include <stdint.h>

// Problem constants (fixed: B=4, H=W=256, C=192, 6 heads, 8x8 windows)
#define BATCH   4
#define HDIM    256
#define WDIM    256
#define CH      192
#define NHEAD   6
#define HEADD   32
#define WS      8
#define NTOK    64
#define NWIN_X  32
#define NWIN_Y  32
#define M_ROWS  (BATCH * HDIM * WDIM)   // 262144
#define QKV_N   (3 * CH)                // 576

// Scratch (__device__ globals: allocation-free rule)
__device__ float g_qkv [(size_t)M_ROWS * QKV_N];   // q|k|v per spatial row
__device__ float g_attn[(size_t)M_ROWS * CH];      // attention out, spatial layout

// ---------------------------------------------------------------------------
// TF32 tensor-core GEMM with bias: C[M,N] = A[M,K] @ W[N,K]^T + bias[N]
// BM=128, BN=64, BK=16; 256 threads (8 warps); warp tile 32x32 (2x4 m16n8k8).
// All calls: M%128==0, N%64==0, K%16==0.
// ---------------------------------------------------------------------------
__device__ __forceinline__ uint32_t f2tf32(float f) {
    uint32_t r;
    asm("cvt.rna.tf32.f32 %0, %1;" : "=r"(r) : "f"(f));
    return r;
}

__device__ __forceinline__ void mma_tf32(float c[4], const uint32_t a[4], const uint32_t b[2]) {
    asm volatile(
        "mma.sync.aligned.m16n8k8.row.col.f32.tf32.tf32.f32 "
        "{%0,%1,%2,%3}, {%4,%5,%6,%7}, {%8,%9}, {%0,%1,%2,%3};\n"
        : "+f"(c[0]), "+f"(c[1]), "+f"(c[2]), "+f"(c[3])
        : "r"(a[0]), "r"(a[1]), "r"(a[2]), "r"(a[3]), "r"(b[0]), "r"(b[1]));
}

#define GBM 128
#define GBN 64
#define GBK 16
#define APAD 136   // 136 % 32 == 8 -> conflict-free fragment LDS
#define BPAD 72    // 72  % 32 == 8

__global__ __launch_bounds__(256)
void gemm_tf32_kernel(const float* __restrict__ A, const float* __restrict__ W,
                      const float* __restrict__ bias, float* __restrict__ C,
                      int M, int N, int K)
{
    __shared__ uint32_t As[GBK][APAD];   // [k][m]
    __shared__ uint32_t Bs[GBK][BPAD];   // [k][n]

    const int t     = threadIdx.x;
    const int lane  = t & 31;
    const int warp  = t >> 5;
    const int warpM = warp & 3;     // 0..3  -> M offset warpM*32
    const int warpN = warp >> 2;    // 0..1  -> N offset warpN*32
    const int g     = lane >> 2;    // 0..7
    const int tg    = lane & 3;     // 0..3

    const int rowBase = blockIdx.y * GBM;
    const int colBase = blockIdx.x * GBN;

    // Tile-load mapping: c4 warp-uniform -> conflict-free STS
    const int lrow = t & 63;          // 0..63
    const int lc4  = (t >> 6) * 4;    // 0,4,8,12

    float acc[2][4][4];
#pragma unroll
    for (int mf = 0; mf < 2; mf++)
#pragma unroll
        for (int nf = 0; nf < 4; nf++)
#pragma unroll
            for (int i = 0; i < 4; i++) acc[mf][nf][i] = 0.f;

    for (int k0 = 0; k0 < K; k0 += GBK) {
        // A tile: 128 rows x 16 k (two passes of 64 rows)
#pragma unroll
        for (int p = 0; p < 2; p++) {
            const int r = p * 64 + lrow;
            const float4 av = *(const float4*)(A + (size_t)(rowBase + r) * K + k0 + lc4);
            As[lc4 + 0][r] = f2tf32(av.x);
            As[lc4 + 1][r] = f2tf32(av.y);
            As[lc4 + 2][r] = f2tf32(av.z);
            As[lc4 + 3][r] = f2tf32(av.w);
        }
        // B tile: 64 n-rows x 16 k
        {
            const float4 wv = *(const float4*)(W + (size_t)(colBase + lrow) * K + k0 + lc4);
            Bs[lc4 + 0][lrow] = f2tf32(wv.x);
            Bs[lc4 + 1][lrow] = f2tf32(wv.y);
            Bs[lc4 + 2][lrow] = f2tf32(wv.z);
            Bs[lc4 + 3][lrow] = f2tf32(wv.w);
        }
        __syncthreads();

#pragma unroll
        for (int kk = 0; kk < GBK; kk += 8) {
            uint32_t a[2][4], b[4][2];
#pragma unroll
            for (int mf = 0; mf < 2; mf++) {
                const int r0 = warpM * 32 + mf * 16;
                a[mf][0] = As[kk + tg    ][r0 + g    ];
                a[mf][1] = As[kk + tg    ][r0 + g + 8];
                a[mf][2] = As[kk + tg + 4][r0 + g    ];
                a[mf][3] = As[kk + tg + 4][r0 + g + 8];
            }
#pragma unroll
            for (int nf = 0; nf < 4; nf++) {
                const int c0 = warpN * 32 + nf * 8;
                b[nf][0] = Bs[kk + tg    ][c0 + g];
                b[nf][1] = Bs[kk + tg + 4][c0 + g];
            }
#pragma unroll
            for (int mf = 0; mf < 2; mf++)
#pragma unroll
                for (int nf = 0; nf < 4; nf++)
                    mma_tf32(acc[mf][nf], a[mf], b[nf]);
        }
        __syncthreads();
    }

    // Epilogue: bias + store (float2 per fragment row)
#pragma unroll
    for (int mf = 0; mf < 2; mf++) {
        const int row0 = rowBase + warpM * 32 + mf * 16 + g;
#pragma unroll
        for (int nf = 0; nf < 4; nf++) {
            const int col = colBase + warpN * 32 + nf * 8 + 2 * tg;
            const float b0 = __ldg(bias + col);
            const float b1 = __ldg(bias + col + 1);
            float2 v0 = make_float2(acc[mf][nf][0] + b0, acc[mf][nf][1] + b1);
            float2 v1 = make_float2(acc[mf][nf][2] + b0, acc[mf][nf][3] + b1);
            *(float2*)(C + (size_t)row0 * N + col)       = v0;
            *(float2*)(C + (size_t)(row0 + 8) * N + col) = v1;
        }
    }
}

// ---------------------------------------------------------------------------
// Window attention: one block per (window, head); 64 threads = 1 per query.
// Window partition/reverse folded into row indexing.
// ---------------------------------------------------------------------------
__global__ __launch_bounds__(64)
void window_attn_kernel(const float* __restrict__ qkv,
                        const float* __restrict__ rpb,   // (225, 6)
                        float* __restrict__ out)
{
    const int win = blockIdx.x;
    const int h   = blockIdx.y;
    const int b   = win >> 10;
    const int wy  = (win >> 5) & 31;
    const int wx  = win & 31;

    const int n   = threadIdx.x;
    const int tyn = n >> 3;
    const int txn = n & 7;

    const int y = wy * WS + tyn;
    const int x = wx * WS + txn;
    const size_t row_n = (size_t)b * (HDIM * WDIM) + (size_t)y * WDIM + x;
    const float* qrow = qkv + row_n * QKV_N + h * HEADD;

    __shared__ float ks[NTOK][HEADD];
    __shared__ float vs[NTOK][HEADD];

    {
        const float4* kp = (const float4*)(qrow + CH);
        const float4* vp = (const float4*)(qrow + 2 * CH);
        float4* kd = (float4*)ks[n];
        float4* vd = (float4*)vs[n];
#pragma unroll
        for (int i = 0; i < HEADD / 4; i++) { kd[i] = kp[i]; vd[i] = vp[i]; }
    }

    float q[HEADD];
    {
        const float4* qp = (const float4*)qrow;
#pragma unroll
        for (int i = 0; i < HEADD / 4; i++) ((float4*)q)[i] = qp[i];
    }
    __syncthreads();

    const float scale = 0.17677669529663687f;   // 1/sqrt(32)

    float s[NTOK];
#pragma unroll
    for (int m = 0; m < NTOK; m++) {
        float a = 0.f;
        const float4* kp = (const float4*)ks[m];
#pragma unroll
        for (int i = 0; i < HEADD / 4; i++) {
            float4 kv = kp[i];
            a = fmaf(q[i * 4 + 0], kv.x, a);
            a = fmaf(q[i * 4 + 1], kv.y, a);
            a = fmaf(q[i * 4 + 2], kv.z, a);
            a = fmaf(q[i * 4 + 3], kv.w, a);
        }
        const int tym = m >> 3;
        const int txm = m & 7;
        const int idx = (tyn - tym + 7) * 15 + (txn - txm + 7);
        s[m] = fmaf(a, scale, __ldg(rpb + idx * NHEAD + h));
    }

    float mx = -1e30f;
#pragma unroll
    for (int m = 0; m < NTOK; m++) mx = fmaxf(mx, s[m]);
    float sum = 0.f;
#pragma unroll
    for (int m = 0; m < NTOK; m++) { s[m] = __expf(s[m] - mx); sum += s[m]; }
    const float inv = 1.0f / sum;

    float o[HEADD];
#pragma unroll
    for (int d = 0; d < HEADD; d++) o[d] = 0.f;
#pragma unroll
    for (int m = 0; m < NTOK; m++) {
        const float p = s[m] * inv;
        const float4* vp = (const float4*)vs[m];
#pragma unroll
        for (int i = 0; i < HEADD / 4; i++) {
            float4 vv = vp[i];
            o[i * 4 + 0] = fmaf(p, vv.x, o[i * 4 + 0]);
            o[i * 4 + 1] = fmaf(p, vv.y, o[i * 4 + 1]);
            o[i * 4 + 2] = fmaf(p, vv.z, o[i * 4 + 2]);
            o[i * 4 + 3] = fmaf(p, vv.w, o[i * 4 + 3]);
        }
    }

    float* orow = out + row_n * CH + h * HEADD;
#pragma unroll
    for (int i = 0; i < HEADD / 4; i++)
        ((float4*)orow)[i] = ((float4*)o)[i];
}

// ---------------------------------------------------------------------------
// launch
// ---------------------------------------------------------------------------
extern "C" void kernel_launch(void* const* d_in, const int* in_sizes, int n_in,
                              void* d_out, int out_size)
{
    const float* x      = (const float*)d_in[0];
    const float* qkv_w  = (const float*)d_in[1];
    const float* qkv_b  = (const float*)d_in[2];
    const float* proj_w = (const float*)d_in[3];
    const float* proj_b = (const float*)d_in[4];
    const float* rpb    = (const float*)d_in[5];
    float* out = (float*)d_out;

    float *qkv_ptr, *attn_ptr;
    cudaGetSymbolAddress((void**)&qkv_ptr,  g_qkv);
    cudaGetSymbolAddress((void**)&attn_ptr, g_attn);

    // 1) QKV projection: (262144 x 192) @ (576 x 192)^T + b -> g_qkv
    gemm_tf32_kernel<<<dim3(QKV_N / GBN, M_ROWS / GBM), 256>>>(
        x, qkv_w, qkv_b, qkv_ptr, M_ROWS, QKV_N, CH);

    // 2) Window attention per (window, head) -> g_attn (spatial layout)
    window_attn_kernel<<<dim3(BATCH * NWIN_Y * NWIN_X, NHEAD), 64>>>(
        qkv_ptr, rpb, attn_ptr);

    // 3) Output projection: (262144 x 192) @ (192 x 192)^T + b -> out
    gemm_tf32_kernel<<<dim3(CH / GBN, M_ROWS / GBM), 256>>>(
        attn_ptr, proj_w, proj_b, out, M_ROWS, CH, CH);
}

// round 7
// speedup vs baseline: 1.8028x; 1.4688x over previous
#include <cuda_runtime.h>
#include <cuda_bf16.h>
#include <math.h>
#include <stdint.h>

// Problem constants (fixed: B=4, H=W=256, C=192, 6 heads, 8x8 windows)
#define BATCH   4
#define HDIM    256
#define WDIM    256
#define CH      192
#define NHEAD   6
#define HEADD   32
#define WS      8
#define NTOK    64
#define M_ROWS  (BATCH * HDIM * WDIM)   // 262144
#define QKV_N   (3 * CH)                // 576
#define K192    192

// Scratch (__device__ globals: allocation-free rule)
__device__ float g_qkv [(size_t)M_ROWS * QKV_N];
__device__ float g_attn[(size_t)M_ROWS * CH];

__device__ __forceinline__ uint32_t f2tf32(float f) {
    uint32_t r;
    asm("cvt.rna.tf32.f32 %0, %1;" : "=r"(r) : "f"(f));
    return r;
}
__device__ __forceinline__ void mma_tf32(float c[4], const uint32_t a[4], const uint32_t b[2]) {
    asm volatile(
        "mma.sync.aligned.m16n8k8.row.col.f32.tf32.tf32.f32 "
        "{%0,%1,%2,%3}, {%4,%5,%6,%7}, {%8,%9}, {%0,%1,%2,%3};\n"
        : "+f"(c[0]), "+f"(c[1]), "+f"(c[2]), "+f"(c[3])
        : "r"(a[0]), "r"(a[1]), "r"(a[2]), "r"(a[3]), "r"(b[0]), "r"(b[1]));
}

// ---------------------------------------------------------------------------
// TF32 mma GEMM v2: C[M,Ntot] = A[M,192] @ W[Ntot,192]^T + bias
// BM=128, BN=64, BK=32; 128 threads (4 warps); warp tile 32x64 (2x8 m16n8k8).
// A smem [m][k] pad-36 (STS.128 stage, conflict-free LDS.32 frags).
// B smem paired: word = grp*514 + n*8 + tg*2 + half -> LDS.64 frags.
// Double-buffered smem + register prefetch; K=192 fully unrolled (6 tiles).
// ---------------------------------------------------------------------------
#define A_BUF (128 * 36)      // floats per A buffer
#define B_BUF 2056            // floats per B buffer (4 groups * 514)
#define SMEM_FLOATS (2 * A_BUF + 2 * B_BUF)
#define SMEM_BYTES  (SMEM_FLOATS * 4)

__global__ __launch_bounds__(128, 3)
void gemm_tf32v2(const float* __restrict__ A, const float* __restrict__ W,
                 const float* __restrict__ bias, float* __restrict__ C,
                 int Ntot)
{
    extern __shared__ float smem[];
    const int t    = threadIdx.x;
    const int lane = t & 31;
    const int warp = t >> 5;
    const int g    = lane >> 2;   // 0..7
    const int tg   = lane & 3;    // 0..3

    const size_t rowBase = (size_t)blockIdx.y * 128;
    const int    colBase = blockIdx.x * 64;

    // staging mapping
    const int rA = t >> 3;        // 0..15
    const int c4 = t & 7;         // 0..7
    const int grp  = c4 >> 1;     // B k-group
    const int half = c4 & 1;      // B half (k<4 vs k>=4)

    const float* Ap = A + (rowBase + rA) * K192 + c4 * 4;
    const float* Wp = W + ((size_t)(colBase + rA)) * K192 + c4 * 4;

    float4 av[8], bv[4];

    float acc[2][8][4];
#pragma unroll
    for (int mf = 0; mf < 2; mf++)
#pragma unroll
        for (int nf = 0; nf < 8; nf++)
#pragma unroll
            for (int i = 0; i < 4; i++) acc[mf][nf][i] = 0.f;

    // ---- prologue: load + store tile 0
#pragma unroll
    for (int i = 0; i < 8; i++) av[i] = *(const float4*)(Ap + (size_t)i * 16 * K192);
#pragma unroll
    for (int i = 0; i < 4; i++) bv[i] = *(const float4*)(Wp + (size_t)i * 16 * K192);
    {
        float* Ab = smem;
        float* Bb = smem + 2 * A_BUF;
#pragma unroll
        for (int i = 0; i < 8; i++) {
            uint4 u;
            u.x = f2tf32(av[i].x); u.y = f2tf32(av[i].y);
            u.z = f2tf32(av[i].z); u.w = f2tf32(av[i].w);
            *(uint4*)(Ab + (rA + i * 16) * 36 + c4 * 4) = u;
        }
#pragma unroll
        for (int i = 0; i < 4; i++) {
            uint32_t* q = (uint32_t*)(Bb + grp * 514 + (rA + i * 16) * 8 + half);
            q[0] = f2tf32(bv[i].x);
            q[2] = f2tf32(bv[i].y);
            q[4] = f2tf32(bv[i].z);
            q[6] = f2tf32(bv[i].w);
        }
    }
    __syncthreads();

#pragma unroll
    for (int kt = 0; kt < 6; kt++) {
        // prefetch next tile into regs (hidden under mma)
        if (kt < 5) {
            const float* Apn = Ap + (kt + 1) * 32;
            const float* Wpn = Wp + (kt + 1) * 32;
#pragma unroll
            for (int i = 0; i < 8; i++) av[i] = *(const float4*)(Apn + (size_t)i * 16 * K192);
#pragma unroll
            for (int i = 0; i < 4; i++) bv[i] = *(const float4*)(Wpn + (size_t)i * 16 * K192);
        }

        const uint32_t* Ab = (const uint32_t*)(smem + (kt & 1) * A_BUF);
        const uint32_t* Bb = (const uint32_t*)(smem + 2 * A_BUF + (kt & 1) * B_BUF);

#pragma unroll
        for (int g8 = 0; g8 < 4; g8++) {
            uint32_t a[2][4], b[8][2];
#pragma unroll
            for (int mf = 0; mf < 2; mf++) {
                const uint32_t* ap = Ab + (warp * 32 + mf * 16 + g) * 36 + g8 * 8 + tg;
                a[mf][0] = ap[0];
                a[mf][1] = ap[8 * 36];
                a[mf][2] = ap[4];
                a[mf][3] = ap[8 * 36 + 4];
            }
#pragma unroll
            for (int nf = 0; nf < 8; nf++) {
                const uint2 bb = *(const uint2*)(Bb + g8 * 514 + (nf * 8 + g) * 8 + tg * 2);
                b[nf][0] = bb.x; b[nf][1] = bb.y;
            }
#pragma unroll
            for (int mf = 0; mf < 2; mf++)
#pragma unroll
                for (int nf = 0; nf < 8; nf++)
                    mma_tf32(acc[mf][nf], a[mf], b[nf]);
        }

        // store prefetched tile into alternate buffer
        if (kt < 5) {
            float* Abn = smem + ((kt + 1) & 1) * A_BUF;
            float* Bbn = smem + 2 * A_BUF + ((kt + 1) & 1) * B_BUF;
#pragma unroll
            for (int i = 0; i < 8; i++) {
                uint4 u;
                u.x = f2tf32(av[i].x); u.y = f2tf32(av[i].y);
                u.z = f2tf32(av[i].z); u.w = f2tf32(av[i].w);
                *(uint4*)(Abn + (rA + i * 16) * 36 + c4 * 4) = u;
            }
#pragma unroll
            for (int i = 0; i < 4; i++) {
                uint32_t* q = (uint32_t*)(Bbn + grp * 514 + (rA + i * 16) * 8 + half);
                q[0] = f2tf32(bv[i].x);
                q[2] = f2tf32(bv[i].y);
                q[4] = f2tf32(bv[i].z);
                q[6] = f2tf32(bv[i].w);
            }
        }
        __syncthreads();
    }

    // ---- epilogue: bias + store
#pragma unroll
    for (int mf = 0; mf < 2; mf++) {
        const size_t row0 = rowBase + warp * 32 + mf * 16 + g;
#pragma unroll
        for (int nf = 0; nf < 8; nf++) {
            const int col = colBase + nf * 8 + 2 * tg;
            const float b0 = __ldg(bias + col);
            const float b1 = __ldg(bias + col + 1);
            float2 v0 = make_float2(acc[mf][nf][0] + b0, acc[mf][nf][1] + b1);
            float2 v1 = make_float2(acc[mf][nf][2] + b0, acc[mf][nf][3] + b1);
            *(float2*)(C + row0 * Ntot + col)       = v0;
            *(float2*)(C + (row0 + 8) * Ntot + col) = v1;
        }
    }
}

// ---------------------------------------------------------------------------
// Window attention, split-2: 128 threads/block = 64 queries x 2 key-halves.
// Thread (n, half) handles keys [half*32, half*32+32); softmax stats and the
// output vector are combined with the partner thread via shfl_xor(.,1).
// ---------------------------------------------------------------------------
__global__ __launch_bounds__(128)
void window_attn_kernel(const float* __restrict__ qkv,
                        const float* __restrict__ rpb,   // (225, 6)
                        float* __restrict__ out)
{
    const int win = blockIdx.x;
    const int h   = blockIdx.y;
    const int b   = win >> 10;
    const int wy  = (win >> 5) & 31;
    const int wx  = win & 31;

    const int t    = threadIdx.x;
    const int n    = t >> 1;        // query token 0..63
    const int half = t & 1;         // key half
    const int tyn  = n >> 3;
    const int txn  = n & 7;

    const int y = wy * WS + tyn;
    const int x = wx * WS + txn;
    const size_t row_n = (size_t)b * (HDIM * WDIM) + (size_t)y * WDIM + x;
    const float* qrow = qkv + row_n * QKV_N + h * HEADD;

    __shared__ float ks[NTOK][HEADD];
    __shared__ float vs[NTOK][HEADD];

    // Two threads stage each token's k,v (16 floats each half).
    {
        const float4* kp = (const float4*)(qrow + CH      + half * 16);
        const float4* vp = (const float4*)(qrow + 2 * CH  + half * 16);
        float4* kd = (float4*)(ks[n] + half * 16);
        float4* vd = (float4*)(vs[n] + half * 16);
#pragma unroll
        for (int i = 0; i < 4; i++) { kd[i] = kp[i]; vd[i] = vp[i]; }
    }

    float q[HEADD];
    {
        const float4* qp = (const float4*)qrow;
#pragma unroll
        for (int i = 0; i < HEADD / 4; i++) ((float4*)q)[i] = qp[i];
    }
    __syncthreads();

    const float scale = 0.17677669529663687f;   // 1/sqrt(32)
    const int mBase = half * 32;

    float s[32];
#pragma unroll
    for (int j = 0; j < 32; j++) {
        const int m = mBase + j;
        float a = 0.f;
        const float4* kp = (const float4*)ks[m];
#pragma unroll
        for (int i = 0; i < HEADD / 4; i++) {
            float4 kv = kp[i];
            a = fmaf(q[i * 4 + 0], kv.x, a);
            a = fmaf(q[i * 4 + 1], kv.y, a);
            a = fmaf(q[i * 4 + 2], kv.z, a);
            a = fmaf(q[i * 4 + 3], kv.w, a);
        }
        const int tym = m >> 3;
        const int txm = m & 7;
        const int idx = (tyn - tym + 7) * 15 + (txn - txm + 7);
        s[j] = fmaf(a, scale, __ldg(rpb + idx * NHEAD + h));
    }

    // softmax stats across both halves
    float mx = -1e30f;
#pragma unroll
    for (int j = 0; j < 32; j++) mx = fmaxf(mx, s[j]);
    mx = fmaxf(mx, __shfl_xor_sync(0xFFFFFFFFu, mx, 1));

    float sum = 0.f;
#pragma unroll
    for (int j = 0; j < 32; j++) { s[j] = __expf(s[j] - mx); sum += s[j]; }
    sum += __shfl_xor_sync(0xFFFFFFFFu, sum, 1);
    const float inv = 1.0f / sum;

    float o[HEADD];
#pragma unroll
    for (int d = 0; d < HEADD; d++) o[d] = 0.f;
#pragma unroll
    for (int j = 0; j < 32; j++) {
        const float p = s[j] * inv;
        const float4* vp = (const float4*)vs[mBase + j];
#pragma unroll
        for (int i = 0; i < HEADD / 4; i++) {
            float4 vv = vp[i];
            o[i * 4 + 0] = fmaf(p, vv.x, o[i * 4 + 0]);
            o[i * 4 + 1] = fmaf(p, vv.y, o[i * 4 + 1]);
            o[i * 4 + 2] = fmaf(p, vv.z, o[i * 4 + 2]);
            o[i * 4 + 3] = fmaf(p, vv.w, o[i * 4 + 3]);
        }
    }

    // combine partial outputs with partner, each thread writes its 16 dims
#pragma unroll
    for (int d = 0; d < HEADD; d++)
        o[d] += __shfl_xor_sync(0xFFFFFFFFu, o[d], 1);

    float* orow = out + row_n * CH + h * HEADD + half * 16;
#pragma unroll
    for (int i = 0; i < 4; i++)
        ((float4*)orow)[i] = ((float4*)(o + half * 16))[i];
}

// ---------------------------------------------------------------------------
// launch
// ---------------------------------------------------------------------------
extern "C" void kernel_launch(void* const* d_in, const int* in_sizes, int n_in,
                              void* d_out, int out_size)
{
    const float* x      = (const float*)d_in[0];
    const float* qkv_w  = (const float*)d_in[1];
    const float* qkv_b  = (const float*)d_in[2];
    const float* proj_w = (const float*)d_in[3];
    const float* proj_b = (const float*)d_in[4];
    const float* rpb    = (const float*)d_in[5];
    float* out = (float*)d_out;

    float *qkv_ptr, *attn_ptr;
    cudaGetSymbolAddress((void**)&qkv_ptr,  g_qkv);
    cudaGetSymbolAddress((void**)&attn_ptr, g_attn);

    // Idempotent, called every launch (no static guards allowed).
    cudaFuncSetAttribute(gemm_tf32v2,
                         cudaFuncAttributeMaxDynamicSharedMemorySize, SMEM_BYTES);

    // 1) QKV projection: (262144 x 192) @ (576 x 192)^T + b -> g_qkv
    gemm_tf32v2<<<dim3(QKV_N / 64, M_ROWS / 128), 128, SMEM_BYTES>>>(
        x, qkv_w, qkv_b, qkv_ptr, QKV_N);

    // 2) Window attention per (window, head) -> g_attn (spatial layout)
    window_attn_kernel<<<dim3(BATCH * 32 * 32, NHEAD), 128>>>(
        qkv_ptr, rpb, attn_ptr);

    // 3) Output projection: (262144 x 192) @ (192 x 192)^T + b -> out
    gemm_tf32v2<<<dim3(CH / 64, M_ROWS / 128), 128, SMEM_BYTES>>>(
        attn_ptr, proj_w, proj_b, out, CH);
}